// round 3
// baseline (speedup 1.0000x reference)
#include <cuda_runtime.h>
#include <cstdint>
#include <cstddef>

// ---------------------------------------------------------------------------
// Problem constants
// ---------------------------------------------------------------------------
#define N_INST 2000
#define HDIM   256
#define DDIM   64
#define RDIM   49
#define PARAMS_PER (2 * HDIM * DDIM)      // 32768
#define F2_COLS (RDIM * HDIM)             // 12544
#define KSPLIT 8
#define KCHUNK (F2_COLS / KSPLIT)         // 1568

// Scratch (allowed: __device__ globals, no runtime allocation)
__device__ float g_params[(size_t)N_INST * PARAMS_PER];   // 262 MB
__device__ float g_f2[(size_t)N_INST * F2_COLS];          // 100 MB
__device__ float g_kpart[(size_t)KSPLIT * N_INST * HDIM]; // 16 MB

// ---------------------------------------------------------------------------
// Packed f32x2 helpers (sm_103a: doubles fp32 FMA throughput vs scalar FFMA)
// ---------------------------------------------------------------------------
__device__ __forceinline__ double pk2(float lo, float hi) {
    double d; asm("mov.b64 %0, {%1, %2};" : "=d"(d) : "f"(lo), "f"(hi)); return d;
}
__device__ __forceinline__ double dup2(float a) {
    double d; asm("mov.b64 %0, {%1, %1};" : "=d"(d) : "f"(a)); return d;
}
__device__ __forceinline__ void fma2(double& c, double a, double b) {
    asm("fma.rn.f32x2 %0, %1, %2, %0;" : "+d"(c) : "d"(a), "d"(b));
}
__device__ __forceinline__ float2 upk2(double v) {
    float2 r; asm("mov.b64 {%0, %1}, %2;" : "=f"(r.x), "=f"(r.y) : "d"(v)); return r;
}

__device__ __forceinline__ float warp_sum(float v) {
#pragma unroll
    for (int o = 16; o > 0; o >>= 1) v += __shfl_xor_sync(0xffffffffu, v, o);
    return v;
}

// ---------------------------------------------------------------------------
// SGEMM: C[M x N] = A[M x K] * B[K x N] (+bias), 128x128x16 tiles, 256 thr,
// 8x8 register tile per thread in f32x2 pairs, register-prefetch double buffer,
// optional split-K via blockIdx.z (each z writes its own partial slab of C).
// N tiles must divide evenly (true here: 32768%128==0, 256%128==0).
// ---------------------------------------------------------------------------
__global__ void __launch_bounds__(256, 2)
sgemm128(const float* __restrict__ A, int lda,
         const float* __restrict__ B, int ldb,
         float* __restrict__ C, int ldc,
         int M, int kChunk, int Ktotal,
         const float* __restrict__ bias)
{
    __shared__ float As[16][128];
    __shared__ float Bs[16][128];

    const int tid = threadIdx.x;
    const int tx = tid & 15;      // col group
    const int ty = tid >> 4;      // row group
    const int mBase = blockIdx.y * 128;
    const int nBase = blockIdx.x * 128;

    const int kStart = blockIdx.z * kChunk;
    const int kEnd = min(Ktotal, kStart + kChunk);
    C += (size_t)blockIdx.z * (size_t)M * (size_t)ldc;

    // loader mapping: A tile = 128 rows x 16 k  (512 float4), transposed store
    const int aRow0 = tid >> 2,          aK0 = (tid & 3) * 4;
    const int aRow1 = (tid + 256) >> 2,  aK1 = ((tid + 256) & 3) * 4;
    //                 B tile = 16 k x 128 cols (512 float4), direct store
    const int bK0 = tid >> 5,            bC0 = (tid & 31) * 4;
    const int bK1 = (tid + 256) >> 5,    bC1 = ((tid + 256) & 31) * 4;

    const float4 f4z = make_float4(0.f, 0.f, 0.f, 0.f);

    double acc[8][4];
#pragma unroll
    for (int i = 0; i < 8; i++)
#pragma unroll
        for (int j = 0; j < 4; j++) acc[i][j] = 0.0;

    float4 va0, va1, vb0, vb1;
    {   // prologue load
        int r0 = mBase + aRow0, r1 = mBase + aRow1;
        va0 = (r0 < M) ? *(const float4*)&A[(size_t)r0 * lda + kStart + aK0] : f4z;
        va1 = (r1 < M) ? *(const float4*)&A[(size_t)r1 * lda + kStart + aK1] : f4z;
        vb0 = *(const float4*)&B[(size_t)(kStart + bK0) * ldb + nBase + bC0];
        vb1 = *(const float4*)&B[(size_t)(kStart + bK1) * ldb + nBase + bC1];
    }

    for (int kt = kStart; kt < kEnd; kt += 16) {
        // stage regs -> smem
        As[aK0 + 0][aRow0] = va0.x; As[aK0 + 1][aRow0] = va0.y;
        As[aK0 + 2][aRow0] = va0.z; As[aK0 + 3][aRow0] = va0.w;
        As[aK1 + 0][aRow1] = va1.x; As[aK1 + 1][aRow1] = va1.y;
        As[aK1 + 2][aRow1] = va1.z; As[aK1 + 3][aRow1] = va1.w;
        *(float4*)&Bs[bK0][bC0] = vb0;
        *(float4*)&Bs[bK1][bC1] = vb1;
        __syncthreads();

        const int ktn = kt + 16;
        if (ktn < kEnd) {   // prefetch next tile while computing this one
            int r0 = mBase + aRow0, r1 = mBase + aRow1;
            va0 = (r0 < M) ? *(const float4*)&A[(size_t)r0 * lda + ktn + aK0] : f4z;
            va1 = (r1 < M) ? *(const float4*)&A[(size_t)r1 * lda + ktn + aK1] : f4z;
            vb0 = *(const float4*)&B[(size_t)(ktn + bK0) * ldb + nBase + bC0];
            vb1 = *(const float4*)&B[(size_t)(ktn + bK1) * ldb + nBase + bC1];
        }

#pragma unroll
        for (int k = 0; k < 16; k++) {
            float4 a0 = *(float4*)&As[k][ty * 4];
            float4 a1 = *(float4*)&As[k][64 + ty * 4];
            float4 b0 = *(float4*)&Bs[k][tx * 4];
            float4 b1 = *(float4*)&Bs[k][64 + tx * 4];
            double pb[4] = { pk2(b0.x, b0.y), pk2(b0.z, b0.w),
                             pk2(b1.x, b1.y), pk2(b1.z, b1.w) };
            float av[8] = { a0.x, a0.y, a0.z, a0.w, a1.x, a1.y, a1.z, a1.w };
#pragma unroll
            for (int i = 0; i < 8; i++) {
                double da = dup2(av[i]);
                fma2(acc[i][0], da, pb[0]);
                fma2(acc[i][1], da, pb[1]);
                fma2(acc[i][2], da, pb[2]);
                fma2(acc[i][3], da, pb[3]);
            }
        }
        __syncthreads();
    }

    // epilogue
#pragma unroll
    for (int i = 0; i < 8; i++) {
        int r = mBase + ((i < 4) ? (ty * 4 + i) : (64 + ty * 4 + (i - 4)));
        if (r >= M) continue;
        float2 c01 = upk2(acc[i][0]);
        float2 c23 = upk2(acc[i][1]);
        float2 c45 = upk2(acc[i][2]);
        float2 c67 = upk2(acc[i][3]);
        int cb0 = nBase + tx * 4;
        int cb1 = cb0 + 64;
        if (bias) {
            c01.x += bias[cb0 + 0]; c01.y += bias[cb0 + 1];
            c23.x += bias[cb0 + 2]; c23.y += bias[cb0 + 3];
            c45.x += bias[cb1 + 0]; c45.y += bias[cb1 + 1];
            c67.x += bias[cb1 + 2]; c67.y += bias[cb1 + 3];
        }
        float4 o0 = make_float4(c01.x, c01.y, c23.x, c23.y);
        float4 o1 = make_float4(c45.x, c45.y, c67.x, c67.y);
        *(float4*)&C[(size_t)r * ldc + cb0] = o0;
        *(float4*)&C[(size_t)r * ldc + cb1] = o1;
    }
}

// ---------------------------------------------------------------------------
// Fused per-instance dynamic conv:
//   f1 = feats(49x256) @ p1(256x64);  LN_D + relu
//   f2 = f1(49x64)     @ p2(64x256);  LN_H + relu  -> g_f2[n] (flattened r*256+h)
// One CTA (256 thr) per instance. Everything staged in SMEM.
// ---------------------------------------------------------------------------
#define SF_LD 264   // 256 + 8 pad (conflict-free column reads: 264 % 32 == 8)
#define DC_SF_FLOATS (RDIM * SF_LD)                 // 12936
#define DC_SP_FLOATS (HDIM * DDIM)                  // 16384
#define DC_SX_FLOATS (RDIM * DDIM)                  // 3136
#define DC_SMEM_BYTES ((DC_SF_FLOATS + DC_SP_FLOATS + DC_SX_FLOATS) * 4)  // 129824

__global__ void __launch_bounds__(256)
dynconv_kernel(const float* __restrict__ roi,   // (49, 2000, 256)
               const float* __restrict__ g1, const float* __restrict__ b1,
               const float* __restrict__ g2, const float* __restrict__ b2)
{
    extern __shared__ float sh[];
    float* sF = sh;                              // feats then f2 : 49 x SF_LD
    float* sP = sh + DC_SF_FLOATS;               // p1 then p2    : 16384
    float* sX = sh + DC_SF_FLOATS + DC_SP_FLOATS;// f1            : 49 x 64

    const int n = blockIdx.x;
    const int tid = threadIdx.x;
    const int lane = tid & 31;
    const int warp = tid >> 5;

    // ---- load feats[n] (49 x 256) and p1 (16384) ----
    {
        const float4* prow = (const float4*)(g_params + (size_t)n * PARAMS_PER);
#pragma unroll 1
        for (int i = tid; i < RDIM * 64; i += 256) {           // 3136 float4
            int r = i >> 6, c4 = i & 63;
            const float4* src = (const float4*)(roi + ((size_t)r * N_INST + n) * HDIM);
            ((float4*)(sF + r * SF_LD))[c4] = src[c4];
        }
#pragma unroll 1
        for (int i = tid; i < DC_SP_FLOATS / 4; i += 256)
            ((float4*)sP)[i] = prow[i];
    }
    __syncthreads();

    // ---- bmm1: f1[r][d] = sum_h feats[r][h] * p1[h][d] ----
    {
        const int d0 = (tid & 7) * 8;
        const int r1 = tid >> 3;            // 0..31
        const int r2 = r1 + 32;             // 32..63
        const bool has2 = (r2 < RDIM);
        float a1c[8] = {0,0,0,0,0,0,0,0};
        float a2c[8] = {0,0,0,0,0,0,0,0};
#pragma unroll 4
        for (int h = 0; h < HDIM; h++) {
            float4 b0 = *(float4*)&sP[h * DDIM + d0];
            float4 b1v = *(float4*)&sP[h * DDIM + d0 + 4];
            float a1 = sF[r1 * SF_LD + h];
            float a2 = has2 ? sF[r2 * SF_LD + h] : 0.f;
            a1c[0] = fmaf(a1, b0.x, a1c[0]); a1c[1] = fmaf(a1, b0.y, a1c[1]);
            a1c[2] = fmaf(a1, b0.z, a1c[2]); a1c[3] = fmaf(a1, b0.w, a1c[3]);
            a1c[4] = fmaf(a1, b1v.x, a1c[4]); a1c[5] = fmaf(a1, b1v.y, a1c[5]);
            a1c[6] = fmaf(a1, b1v.z, a1c[6]); a1c[7] = fmaf(a1, b1v.w, a1c[7]);
            a2c[0] = fmaf(a2, b0.x, a2c[0]); a2c[1] = fmaf(a2, b0.y, a2c[1]);
            a2c[2] = fmaf(a2, b0.z, a2c[2]); a2c[3] = fmaf(a2, b0.w, a2c[3]);
            a2c[4] = fmaf(a2, b1v.x, a2c[4]); a2c[5] = fmaf(a2, b1v.y, a2c[5]);
            a2c[6] = fmaf(a2, b1v.z, a2c[6]); a2c[7] = fmaf(a2, b1v.w, a2c[7]);
        }
        *(float4*)&sX[r1 * DDIM + d0]     = make_float4(a1c[0], a1c[1], a1c[2], a1c[3]);
        *(float4*)&sX[r1 * DDIM + d0 + 4] = make_float4(a1c[4], a1c[5], a1c[6], a1c[7]);
        if (has2) {
            *(float4*)&sX[r2 * DDIM + d0]     = make_float4(a2c[0], a2c[1], a2c[2], a2c[3]);
            *(float4*)&sX[r2 * DDIM + d0 + 4] = make_float4(a2c[4], a2c[5], a2c[6], a2c[7]);
        }
    }
    __syncthreads();

    // ---- load p2 (overwrites sP; bmm1 done) ----
    {
        const float4* prow = (const float4*)(g_params + (size_t)n * PARAMS_PER + HDIM * DDIM);
#pragma unroll 1
        for (int i = tid; i < DC_SP_FLOATS / 4; i += 256)
            ((float4*)sP)[i] = prow[i];
    }

    // ---- LN over D=64 + relu, in place on sX ----
    {
        float gg0 = g1[lane], gg1 = g1[lane + 32];
        float bb0 = b1[lane], bb1 = b1[lane + 32];
        for (int r = warp; r < RDIM; r += 8) {
            float v0 = sX[r * DDIM + lane];
            float v1 = sX[r * DDIM + lane + 32];
            float s = warp_sum(v0 + v1);
            float sq = warp_sum(v0 * v0 + v1 * v1);
            float m = s * (1.f / DDIM);
            float var = sq * (1.f / DDIM) - m * m;
            float inv = rsqrtf(var + 1e-5f);
            sX[r * DDIM + lane]      = fmaxf((v0 - m) * inv * gg0 + bb0, 0.f);
            sX[r * DDIM + lane + 32] = fmaxf((v1 - m) * inv * gg1 + bb1, 0.f);
        }
    }
    __syncthreads();

    // ---- bmm2: f2[r][h] = sum_d f1[r][d] * p2[d][h]  -> sF ----
    {
        const int h0 = (tid & 31) * 8;
        const int rb = tid >> 5;            // 0..7
#pragma unroll 1
        for (int p = 0; p < 4; p++) {
            int r1 = rb + 16 * p;
            if (r1 >= RDIM) break;
            int r2 = r1 + 8;
            bool has2 = (r2 < RDIM);
            float a1c[8] = {0,0,0,0,0,0,0,0};
            float a2c[8] = {0,0,0,0,0,0,0,0};
#pragma unroll 4
            for (int k = 0; k < DDIM; k++) {
                float4 b0 = *(float4*)&sP[k * HDIM + h0];
                float4 b1v = *(float4*)&sP[k * HDIM + h0 + 4];
                float a1 = sX[r1 * DDIM + k];
                float a2 = has2 ? sX[r2 * DDIM + k] : 0.f;
                a1c[0] = fmaf(a1, b0.x, a1c[0]); a1c[1] = fmaf(a1, b0.y, a1c[1]);
                a1c[2] = fmaf(a1, b0.z, a1c[2]); a1c[3] = fmaf(a1, b0.w, a1c[3]);
                a1c[4] = fmaf(a1, b1v.x, a1c[4]); a1c[5] = fmaf(a1, b1v.y, a1c[5]);
                a1c[6] = fmaf(a1, b1v.z, a1c[6]); a1c[7] = fmaf(a1, b1v.w, a1c[7]);
                a2c[0] = fmaf(a2, b0.x, a2c[0]); a2c[1] = fmaf(a2, b0.y, a2c[1]);
                a2c[2] = fmaf(a2, b0.z, a2c[2]); a2c[3] = fmaf(a2, b0.w, a2c[3]);
                a2c[4] = fmaf(a2, b1v.x, a2c[4]); a2c[5] = fmaf(a2, b1v.y, a2c[5]);
                a2c[6] = fmaf(a2, b1v.z, a2c[6]); a2c[7] = fmaf(a2, b1v.w, a2c[7]);
            }
#pragma unroll
            for (int j = 0; j < 8; j++) sF[r1 * SF_LD + h0 + j] = a1c[j];
            if (has2) {
#pragma unroll
                for (int j = 0; j < 8; j++) sF[r2 * SF_LD + h0 + j] = a2c[j];
            }
        }
    }
    __syncthreads();

    // ---- LN over H=256 + relu, write flattened to g_f2[n] ----
    {
        float gA[8], bA[8];
#pragma unroll
        for (int j = 0; j < 8; j++) { gA[j] = g2[lane + 32 * j]; bA[j] = b2[lane + 32 * j]; }
        float* dst = g_f2 + (size_t)n * F2_COLS;
        for (int r = warp; r < RDIM; r += 8) {
            float v[8];
            float s = 0.f, sq = 0.f;
#pragma unroll
            for (int j = 0; j < 8; j++) {
                v[j] = sF[r * SF_LD + lane + 32 * j];
                s += v[j]; sq += v[j] * v[j];
            }
            s = warp_sum(s); sq = warp_sum(sq);
            float m = s * (1.f / HDIM);
            float var = sq * (1.f / HDIM) - m * m;
            float inv = rsqrtf(var + 1e-5f);
#pragma unroll
            for (int j = 0; j < 8; j++) {
                int h = lane + 32 * j;
                dst[r * HDIM + h] = fmaxf((v[j] - m) * inv * gA[j] + bA[j], 0.f);
            }
        }
    }
}

// ---------------------------------------------------------------------------
// Reduce split-K partials + bias, LN over H=256 + relu -> output (2000 x 256)
// ---------------------------------------------------------------------------
__global__ void __launch_bounds__(256)
reduce_ln3(const float* __restrict__ b_out,
           const float* __restrict__ g3, const float* __restrict__ b3,
           float* __restrict__ out)
{
    const int lane = threadIdx.x & 31;
    const int warp = threadIdx.x >> 5;
    const int row = blockIdx.x * 8 + warp;          // grid 250 * 8 = 2000
    float v[8];
    float s = 0.f, sq = 0.f;
#pragma unroll
    for (int j = 0; j < 8; j++) {
        int h = lane + 32 * j;
        float a = b_out[h];
#pragma unroll
        for (int z = 0; z < KSPLIT; z++)
            a += g_kpart[((size_t)z * N_INST + row) * HDIM + h];
        v[j] = a; s += a; sq += a * a;
    }
    s = warp_sum(s); sq = warp_sum(sq);
    float m = s * (1.f / HDIM);
    float var = sq * (1.f / HDIM) - m * m;
    float inv = rsqrtf(var + 1e-5f);
#pragma unroll
    for (int j = 0; j < 8; j++) {
        int h = lane + 32 * j;
        float o = (v[j] - m) * inv * g3[h] + b3[h];
        out[(size_t)row * HDIM + h] = fmaxf(o, 0.f);
    }
}

// ---------------------------------------------------------------------------
extern "C" void kernel_launch(void* const* d_in, const int* in_sizes, int n_in,
                              void* d_out, int out_size)
{
    (void)in_sizes; (void)n_in; (void)out_size;
    const float* pro   = (const float*)d_in[0];   // (1, 2000, 256)
    const float* roi   = (const float*)d_in[1];   // (49, 2000, 256)
    const float* W_dyn = (const float*)d_in[2];   // (256, 32768)
    const float* b_dyn = (const float*)d_in[3];   // (32768,)
    const float* W_out = (const float*)d_in[4];   // (12544, 256)
    const float* b_out = (const float*)d_in[5];   // (256,)
    const float* g1 = (const float*)d_in[6];
    const float* b1 = (const float*)d_in[7];
    const float* g2 = (const float*)d_in[8];
    const float* b2 = (const float*)d_in[9];
    const float* g3 = (const float*)d_in[10];
    const float* b3 = (const float*)d_in[11];
    float* out = (float*)d_out;

    float *p_params = nullptr, *p_f2 = nullptr, *p_kpart = nullptr;
    cudaGetSymbolAddress((void**)&p_params, g_params);
    cudaGetSymbolAddress((void**)&p_f2, g_f2);
    cudaGetSymbolAddress((void**)&p_kpart, g_kpart);

    cudaFuncSetAttribute(dynconv_kernel,
                         cudaFuncAttributeMaxDynamicSharedMemorySize, DC_SMEM_BYTES);

    // K1: params = pro @ W_dyn + b_dyn            (2000 x 32768, K=256)
    sgemm128<<<dim3(PARAMS_PER / 128, 16, 1), 256>>>(
        pro, HDIM, W_dyn, PARAMS_PER, p_params, PARAMS_PER,
        N_INST, HDIM, HDIM, b_dyn);

    // K2: fused per-instance dynamic conv -> g_f2 (2000 x 12544)
    dynconv_kernel<<<N_INST, 256, DC_SMEM_BYTES>>>(roi, g1, b1, g2, b2);

    // K3: partials of F2 @ W_out, split-K=8       (2000 x 256, K=12544)
    sgemm128<<<dim3(HDIM / 128, 16, KSPLIT), 256>>>(
        p_f2, F2_COLS, W_out, HDIM, p_kpart, HDIM,
        N_INST, KCHUNK, F2_COLS, nullptr);

    // K4: reduce partials + bias + LN + relu -> out
    reduce_ln3<<<N_INST / 8, 256>>>(b_out, g3, b3, out);
}